// round 1
// baseline (speedup 1.0000x reference)
#include <cuda_runtime.h>

// Problem constants
#define NQ   20
#define NL   8
#define BB   32
#define DIM  (1u << NQ)        // 1048576
#define NF4  (DIM / 4)         // 262144 float4s per statevector
#define TPB  256
#define CHUNKS 16              // blocks per batch row in the reduction kernel
#define F4_PER_CHUNK (NF4 / CHUNKS)   // 16384
#define JO 4                   // runtime outer iterations
#define JI 16                  // compile-time inner iterations  (JO*JI*TPB == F4_PER_CHUNK)

// Scratch (static device arrays: no allocation in kernel_launch)
__device__ float g_G[DIM];                       // G[i] = prod_l noise[l,i]^2
__device__ float g_part[BB * CHUNKS * 21];       // per-block partial bit sums (20 qubits + total)

// ---------------------------------------------------------------------------
// Kernel 1: G[i] = prod over 8 layers of noise[l,i]^2   (vectorized float4)
// ---------------------------------------------------------------------------
__global__ void __launch_bounds__(TPB) k_prodG(const float* __restrict__ noise) {
    unsigned i = blockIdx.x * TPB + threadIdx.x;      // float4 index, grid covers NF4 exactly
    const float4* n4 = reinterpret_cast<const float4*>(noise);
    float4 v = n4[i];
    float4 g;
    g.x = v.x * v.x; g.y = v.y * v.y; g.z = v.z * v.z; g.w = v.w * v.w;
#pragma unroll
    for (int l = 1; l < NL; l++) {
        v = n4[(size_t)l * NF4 + i];
        g.x *= v.x * v.x; g.y *= v.y * v.y; g.z *= v.z * v.z; g.w *= v.w * v.w;
    }
    reinterpret_cast<float4*>(g_G)[i] = g;
}

// ---------------------------------------------------------------------------
// Kernel 2: bit-masked reduction.
// Element index i = idx*4 + r,  idx = chunk*16384 + (jo*16+ji)*256 + t.
//   qubit 0,1   <- r        (handled per float4)
//   qubit 2..9  <- t bits   (free: thread total, applied at reduction)
//   qubit 10..13<- ji bits  (compile-time predicated adds)
//   qubit 14,15 <- jo bits  (2 predicated adds per outer iter)
//   qubit 16..19<- chunk bits (free: block total, applied at reduction)
// ---------------------------------------------------------------------------
__global__ void __launch_bounds__(TPB) k_bitsum(const float* __restrict__ amps) {
    const int b     = blockIdx.x & (BB - 1);
    const int chunk = blockIdx.x >> 5;
    const int t     = threadIdx.x;

    const float4* a4 = reinterpret_cast<const float4*>(amps)
                       + (size_t)b * NF4 + (size_t)chunk * F4_PER_CHUNK + t;
    const float4* g4 = reinterpret_cast<const float4*>(g_G)
                       + (size_t)chunk * F4_PER_CHUNK + t;

    float acc0 = 0.f, acc1 = 0.f, accT = 0.f;
    float accJ[6] = {0.f, 0.f, 0.f, 0.f, 0.f, 0.f};

    for (int jo = 0; jo < JO; jo++) {
        float sO = 0.f;
#pragma unroll
        for (int ji = 0; ji < JI; ji++) {
            const int off = (jo * JI + ji) * TPB;
            float4 a = __ldcs(a4 + off);     // streaming: keep G resident in L2
            float4 g = __ldg(g4 + off);
            float w0 = a.x * a.x * g.x;
            float w1 = a.y * a.y * g.y;
            float w2 = a.z * a.z * g.z;
            float w3 = a.w * a.w * g.w;
            float s  = (w0 + w1) + (w2 + w3);
            acc0 += w1 + w3;                 // qubit 0 (r has bit0 set: r=1,3)
            acc1 += w2 + w3;                 // qubit 1 (r=2,3)
            if (ji & 1) accJ[0] += s;        // compile-time predicates
            if (ji & 2) accJ[1] += s;
            if (ji & 4) accJ[2] += s;
            if (ji & 8) accJ[3] += s;
            sO += s;
        }
        if (jo & 1) accJ[4] += sO;
        if (jo & 2) accJ[5] += sO;
        accT += sO;
    }

    float vals[21];
    vals[0] = acc0;
    vals[1] = acc1;
#pragma unroll
    for (int k = 0; k < 8; k++) vals[2 + k] = ((t >> k) & 1) ? accT : 0.f;   // qubits 2..9
#pragma unroll
    for (int m = 0; m < 6; m++) vals[10 + m] = accJ[m];                      // qubits 10..15
#pragma unroll
    for (int m = 0; m < 4; m++) vals[16 + m] = ((chunk >> m) & 1) ? accT : 0.f; // 16..19
    vals[20] = accT;                                                          // grand total

    // warp butterfly reduction of all 21 values
#pragma unroll
    for (int k = 0; k < 21; k++) {
#pragma unroll
        for (int o = 16; o > 0; o >>= 1)
            vals[k] += __shfl_xor_sync(0xffffffffu, vals[k], o);
    }

    __shared__ float red[TPB / 32][21];
    const int wid = t >> 5, lane = t & 31;
    if (lane == 0) {
#pragma unroll
        for (int k = 0; k < 21; k++) red[wid][k] = vals[k];
    }
    __syncthreads();
    if (t < 21) {
        float s = 0.f;
#pragma unroll
        for (int w = 0; w < TPB / 32; w++) s += red[w][t];
        g_part[blockIdx.x * 21 + t] = s;   // deterministic per-block partial
    }
}

// ---------------------------------------------------------------------------
// Kernel 3: reduce partials -> qubit probs -> tanh(qp @ Wi + bi)
// ---------------------------------------------------------------------------
__global__ void k_final(const float* __restrict__ Wi, const float* __restrict__ bi,
                        float* __restrict__ out) {
    __shared__ float Q[BB][21];
    const int t = threadIdx.x;
    if (t < BB * 21) {
        const int b = t / 21, k = t % 21;
        float s = 0.f;
#pragma unroll
        for (int c = 0; c < CHUNKS; c++) s += g_part[(c * BB + b) * 21 + k];
        Q[b][k] = s;
    }
    __syncthreads();
    if (t < BB * NQ) {
        const int b = t / NQ, j = t % NQ;
        const float inv = 1.f / Q[b][20];
        float acc = bi[j];
#pragma unroll
        for (int q = 0; q < NQ; q++) acc += (Q[b][q] * inv) * Wi[q * NQ + j];
        out[t] = tanhf(acc);
    }
}

// ---------------------------------------------------------------------------
// Launch: 3 graph-capturable kernels, no syncs, no allocations.
// Inputs (metadata order): x,W1,b1,W2,b2,W3,b3,amps0,cnot_noise,Wi,bi
// Located defensively by unique element counts.
// ---------------------------------------------------------------------------
extern "C" void kernel_launch(void* const* d_in, const int* in_sizes, int n_in,
                              void* d_out, int out_size) {
    int i_amps = 7, i_noise = 8, i_Wi = 9, i_bi = 10;
    for (int i = 0; i < n_in; i++) {
        const long sz = in_sizes[i];
        if (sz == (long)BB * (long)DIM)      i_amps  = i;  // 33,554,432
        else if (sz == (long)NL * (long)DIM) i_noise = i;  //  8,388,608
        else if (sz == NQ * NQ)              i_Wi    = i;  // 400
        else if (sz == NQ)                   i_bi    = i;  // 20
    }

    const float* noise = (const float*)d_in[i_noise];
    const float* amps  = (const float*)d_in[i_amps];
    const float* Wi    = (const float*)d_in[i_Wi];
    const float* bi    = (const float*)d_in[i_bi];
    float* out         = (float*)d_out;

    k_prodG <<<NF4 / TPB, TPB>>>(noise);        // 1024 blocks
    k_bitsum<<<BB * CHUNKS, TPB>>>(amps);       //  512 blocks
    k_final <<<1, BB * 21>>>(Wi, bi, out);      //  672 threads
}